// round 7
// baseline (speedup 1.0000x reference)
#include <cuda_runtime.h>
#include <cstdint>

#define KS 93          // gaussian kernel size (static, matches reference)
#define NPTS 256       // points per batch
#define W_OUT 512
#define H_OUT 512
#define RPB 8          // rows per block
#define NT 256         // threads per block; thread t -> column colBase + t
#define PAD 127        // left zero-padding of the gaussian table
#define GNP_LEN 348    // nonzero only in [PAD, PAD+93); max index 127+219 = 346

// One block per (batch, 8-row group, 256-col half).  grid = 8*64*2 = 1024.
// 8 warps: warps 0-3 own local slab 0 (cols colBase+0..127), warps 4-7 slab 1.
// Each thread classifies exactly one point (t == point id), once, for both slabs.
__global__ __launch_bounds__(NT)
void density_kernel(const float* __restrict__ labels,
                    const float* __restrict__ sigma_ptr,
                    float* __restrict__ out) {
    const int half    = blockIdx.x & 1;
    const int rowBase = ((blockIdx.x >> 1) & 63) * RPB;
    const int b       = blockIdx.x >> 7;
    const int colBase = half * 256;
    const int t    = threadIdx.x;
    const int warp = t >> 5;
    const int lane = t & 31;
    const int slab = t >> 7;                      // 0 or 1 (phase-2 role)
    const int tl   = t & 127;                     // column within slab

    __shared__ __align__(16) float  sW[NPTS][RPB];   // row weights, indexed by point id
    __shared__ __align__(8)  float2 gnp2[GNP_LEN];   // duplicated-pair gaussian, zero-padded
    __shared__ __align__(8)  int2   lists[2][NPTS];  // (point id, dd) per slab
    __shared__ float wsum[3];
    __shared__ int   cnt[2][8];                      // slab x warp active counts

    // ---- Global loads first (overlap latency with setup math) ------------
    const float2 p = ((const float2*)(labels + (size_t)b * NPTS * 2))[t];
    const float  s = fabsf(sigma_ptr[0]);

    // ---- Gaussian setup (deterministic) ----------------------------------
    const float inv2s2 = 1.0f / (2.0f * s * s);
    float gval = 0.0f;
    if (t < KS) {
        const float a = (float)(t - KS / 2);         // [-46, 46]
        gval = expf(-(a * a) * inv2s2);
    }
    if (warp < 3) {
        float v = gval;
        #pragma unroll
        for (int off = 16; off > 0; off >>= 1) v += __shfl_down_sync(0xffffffffu, v, off);
        if (lane == 0) wsum[warp] = v;
    }
    // zero-fill padded pair table (348 entries, 256 threads)
    gnp2[t < GNP_LEN ? t : 0] = make_float2(0.0f, 0.0f);
    if (t < GNP_LEN - NT) gnp2[NT + t] = make_float2(0.0f, 0.0f);

    // ---- Classification: one point per thread, both slabs ----------------
    const int da = rowBase - (int)truncf(p.x - 46.5f);  // row offset
    const int c0 = (int)truncf(p.y - 46.5f);            // patch first column
    const bool rowAct = (unsigned)(da + RPB - 1) < (unsigned)(KS + RPB - 1);
    int dd0, dd1;
    bool act0, act1;
    {
        const int dc0 = colBase - c0;                   // slab 0 base offset
        const int dc1 = colBase + 128 - c0;             // slab 1 base offset
        act0 = rowAct && ((unsigned)(dc0 + PAD) < (unsigned)(KS + PAD));
        act1 = rowAct && ((unsigned)(dc1 + PAD) < (unsigned)(KS + PAD));
        dd0 = PAD + dc0;
        dd1 = PAD + dc1;
    }
    const unsigned bal0 = __ballot_sync(0xffffffffu, act0);
    const unsigned bal1 = __ballot_sync(0xffffffffu, act1);
    if (lane == 0) {
        cnt[0][warp] = __popc(bal0);
        cnt[1][warp] = __popc(bal1);
    }
    __syncthreads();   // #1: wsum, gnp2 zeros, cnt visible

    // ---- Table write + list writes + M (independent of each other) -------
    if (t < KS) {
        const float g = gval / (wsum[0] + wsum[1] + wsum[2]);
        gnp2[PAD + t] = make_float2(g, g);
    }
    const unsigned ltmask = (1u << lane) - 1u;
    if (act0) {
        int base = __popc(bal0 & ltmask);
        for (int w = 0; w < 8; w++) if (w < warp) base += cnt[0][w];
        lists[0][base] = make_int2(t, dd0);
    }
    if (act1) {
        int base = __popc(bal1 & ltmask);
        for (int w = 0; w < 8; w++) if (w < warp) base += cnt[1][w];
        lists[1][base] = make_int2(t, dd1);
    }
    int M = 0;
    #pragma unroll
    for (int w = 0; w < 8; w++) M += cnt[slab][w];
    __syncthreads();   // #2: table + lists complete

    // ---- Row-weight fill (needs table), once per row-active point --------
    if (rowAct) {
        #pragma unroll
        for (int r = 0; r < RPB; r++)                   // zeros free from padding
            sW[t][r] = gnp2[PAD + da + r].x;
    }
    __syncthreads();   // #3: sW complete

    // ---- Phase 2: packed f32x2 accumulation over this warp's slab list ---
    uint64_t acc0 = 0ull, acc1 = 0ull, acc2 = 0ull, acc3 = 0ull;
    const int2*      lst = lists[slab];

    #pragma unroll 4
    for (int m = 0; m < M; m++) {
        const int2 e = lst[m];                           // broadcast LDS.64
        const ulonglong2* wp = (const ulonglong2*)&sW[e.x][0];
        const ulonglong2 w01 = wp[0];                    // rows 0-3 (2 packed pairs)
        const ulonglong2 w23 = wp[1];                    // rows 4-7
        const uint64_t gv2 = *(const uint64_t*)&gnp2[tl + e.y];  // {gv, gv}
        asm("fma.rn.f32x2 %0, %1, %2, %0;" : "+l"(acc0) : "l"(gv2), "l"(w01.x));
        asm("fma.rn.f32x2 %0, %1, %2, %0;" : "+l"(acc1) : "l"(gv2), "l"(w01.y));
        asm("fma.rn.f32x2 %0, %1, %2, %0;" : "+l"(acc2) : "l"(gv2), "l"(w23.x));
        asm("fma.rn.f32x2 %0, %1, %2, %0;" : "+l"(acc3) : "l"(gv2), "l"(w23.y));
    }

    // ---- Write 8 rows x 256 cols, coalesced ------------------------------
    float* o = out + ((size_t)b * H_OUT + rowBase) * W_OUT + colBase;
    uint32_t lo, hi;
    asm("mov.b64 {%0, %1}, %2;" : "=r"(lo), "=r"(hi) : "l"(acc0));
    o[0 * W_OUT + t] = __uint_as_float(lo);
    o[1 * W_OUT + t] = __uint_as_float(hi);
    asm("mov.b64 {%0, %1}, %2;" : "=r"(lo), "=r"(hi) : "l"(acc1));
    o[2 * W_OUT + t] = __uint_as_float(lo);
    o[3 * W_OUT + t] = __uint_as_float(hi);
    asm("mov.b64 {%0, %1}, %2;" : "=r"(lo), "=r"(hi) : "l"(acc2));
    o[4 * W_OUT + t] = __uint_as_float(lo);
    o[5 * W_OUT + t] = __uint_as_float(hi);
    asm("mov.b64 {%0, %1}, %2;" : "=r"(lo), "=r"(hi) : "l"(acc3));
    o[6 * W_OUT + t] = __uint_as_float(lo);
    o[7 * W_OUT + t] = __uint_as_float(hi);
}

extern "C" void kernel_launch(void* const* d_in, const int* in_sizes, int n_in,
                              void* d_out, int out_size) {
    // metadata order: [0] batch_images (unused by the math),
    //                 [1] batch_labels [8,256,2] f32, [2] sigma scalar f32
    const float* labels = (const float*)d_in[1];
    const float* sigma  = (const float*)d_in[2];
    float* out = (float*)d_out;                   // [8,1,512,512] f32

    density_kernel<<<8 * (H_OUT / RPB) * 2, NT>>>(labels, sigma, out);
}